// round 10
// baseline (speedup 1.0000x reference)
#include <cuda_runtime.h>
#include <stdint.h>
#include <math.h>

#define DD    20
#define TPB   128
#define WPB   4               // warps per block
#define NCTA  456             // 152 SMs x 3 CTAs
#define HST   24              // h smem row stride (floats)
#define XBUF  (64 * DD)       // floats per 64-row supertile buffer
#define HWARP (4 * 16 * HST)  // h floats per warp (4 subtiles)
#define SMEM_DYN (WPB * 2 * XBUF * 4 + WPB * HWARP * 4)   // 40960 + 24576 = 65536B

__device__ double   g_psum[NCTA];
__device__ double   g_pabs[NCTA];
__device__ unsigned g_done = 0;

static __device__ __forceinline__ uint32_t f2tf(float f) {   // exact rna (prologue only)
    uint32_t u; asm("cvt.rna.tf32.f32 %0, %1;" : "=r"(u) : "f"(f)); return u;
}
// rna-to-tf32 via mantissa carry (validated bit-exact vs cvt.rna in R9)
static __device__ __forceinline__ uint32_t rna(float f) {
    return __float_as_uint(f) + 0x1000u;
}
static __device__ __forceinline__ void mma8(float* c, const uint32_t* a, const uint32_t* b) {
    asm volatile("mma.sync.aligned.m16n8k8.row.col.f32.tf32.tf32.f32 "
        "{%0,%1,%2,%3}, {%4,%5,%6,%7}, {%8,%9}, {%0,%1,%2,%3};"
        : "+f"(c[0]), "+f"(c[1]), "+f"(c[2]), "+f"(c[3])
        : "r"(a[0]), "r"(a[1]), "r"(a[2]), "r"(a[3]), "r"(b[0]), "r"(b[1]));
}
static __device__ __forceinline__ uint32_t s2u(const void* p) {
    uint32_t a;
    asm("{ .reg .u64 t; cvta.to.shared.u64 t, %1; cvt.u32.u64 %0, t; }" : "=r"(a) : "l"(p));
    return a;
}
// 64-row supertile prefetch: 5120B/warp = 10 coalesced 16B cp.async per lane
static __device__ __forceinline__ void issue_tile(const char* Xb, long long tile,
                                                  long long ntiles, long long maxoff,
                                                  uint32_t dst, int lane) {
    if (tile >= ntiles) tile = ntiles - 1;
    long long base = tile * 5120 + (long long)lane * 16;
    #pragma unroll
    for (int c = 0; c < 10; c++) {
        long long off = base + c * 512;
        if (off > maxoff) off = maxoff;
        asm volatile("cp.async.cg.shared.global [%0], [%1], 16;"
                     :: "r"(dst + c * 512 + lane * 16), "l"(Xb + off) : "memory");
    }
    asm volatile("cp.async.commit_group;" ::: "memory");
}

__global__ void __launch_bounds__(TPB, 3)
fused_kernel(const float* __restrict__ X, const float* __restrict__ W,
             const float* __restrict__ bvec, const float* __restrict__ Wi,
             long long nrows, float* __restrict__ out) {
    extern __shared__ __align__(16) char smem[];
    float* sX = (float*)smem;                         // WPB*2*XBUF floats
    float* sH = (float*)(smem + WPB * 2 * XBUF * 4);  // WPB*HWARP floats
    __shared__ double s_rs[WPB], s_ra[WPB];
    __shared__ int    s_last;

    const int t = threadIdx.x;
    const int wid = t >> 5, lane = t & 31;
    const int qr = lane >> 2, qc = lane & 3;

    // ---- prologue (overlaid on h arena): M1 = W^T@Wi, c1 = b@Wi + 1 ----
    {
        float* sW  = sH;          // 400
        float* sWi = sW + 400;    // 400
        float* sM1 = sWi + 400;   // 400
        float* sc1 = sM1 + 400;   // 20
        float* sb2 = sc1 + 20;    // 20   (4960B <= 24576B arena)

        for (int i = t; i < 400; i += TPB) { sW[i] = W[i]; sWi[i] = Wi[i]; }
        if (t < DD) sb2[t] = bvec[t];
        __syncthreads();
        for (int e = t; e < 400; e += TPB) {
            int k = e / 20, n = e % 20;
            float a = 0.f;
            #pragma unroll
            for (int j = 0; j < 20; j++) a = fmaf(sW[j*20 + k], sWi[j*20 + n], a);
            sM1[e] = a;
        }
        if (t < DD) {
            float a = 1.f;
            #pragma unroll
            for (int j = 0; j < 20; j++) a = fmaf(sb2[j], sWi[j*20 + t], a);
            sc1[t] = a;
        }
        __syncthreads();
    }

    // ---- constant B fragments (exact rna) + bias C-inits, in regs ----
    uint32_t b1f[3][3][2], b2f[3][3][2];
    float    bi1[3][2], bi2[3][2];
    {
        float* sW  = sH;
        float* sM1 = sW + 800;
        float* sc1 = sM1 + 400;
        float* sb2 = sc1 + 20;
        #pragma unroll
        for (int j = 0; j < 3; j++) {
            int k0 = 8*j + qc, k1 = k0 + 4;
            #pragma unroll
            for (int i = 0; i < 3; i++) {
                int n = 8*i + qr;
                float v0 = (k0 < 20 && n < 20) ? sM1[k0*20 + n] : 0.f;
                float v1 = (k1 < 20 && n < 20) ? sM1[k1*20 + n] : 0.f;
                b1f[j][i][0] = f2tf(v0); b1f[j][i][1] = f2tf(v1);
                float w0 = (k0 < 20 && n < 20) ? sW[n*20 + k0] : 0.f;
                float w1 = (k1 < 20 && n < 20) ? sW[n*20 + k1] : 0.f;
                b2f[j][i][0] = f2tf(w0); b2f[j][i][1] = f2tf(w1);
            }
        }
        #pragma unroll
        for (int i = 0; i < 3; i++) {
            int n0 = 8*i + 2*qc;
            bi1[i][0] = (n0     < 20) ? sc1[n0]     : 0.f;
            bi1[i][1] = (n0 + 1 < 20) ? sc1[n0 + 1] : 0.f;
            bi2[i][0] = (n0     < 20) ? sb2[n0]     : 0.f;
            bi2[i][1] = (n0 + 1 < 20) ? sb2[n0 + 1] : 0.f;
        }
        __syncthreads();   // prologue reads done before arena reused for h
    }

    // ---- mainloop: 64 rows/warp/iter (4 subtile streams), ping-pong buffers ----
    const long long ntiles = (nrows + 63) >> 6;
    const long long gw = (long long)blockIdx.x * WPB + wid;
    const long long nw = (long long)gridDim.x * WPB;
    const long long maxoff = nrows * 80 - 16;
    const char* Xb = (const char*)X;

    float* px0 = sX + wid * (2 * XBUF);
    float* px1 = px0 + XBUF;
    const uint32_t d0 = s2u(px0), d1 = s2u(px1);
    float* hw = sH + wid * HWARP;

    float aS0 = 0.f, aS1 = 0.f, aA0 = 0.f, aA1 = 0.f;
    int p = 0;

    if (gw < ntiles) issue_tile(Xb, gw, ntiles, maxoff, d0, lane);

    for (long long tl = gw; tl < ntiles; tl += nw) {
        issue_tile(Xb, tl + nw, ntiles, maxoff, p ? d0 : d1, lane);
        asm volatile("cp.async.wait_group 1;" ::: "memory");
        __syncwarp();

        const float* xs = p ? px1 : px0;
        const long long Rt = tl << 6;

        // ---- phase 1: load A fragments for all 4 subtiles ----
        uint32_t a[4][3][4];
        #pragma unroll
        for (int s = 0; s < 4; s++) {
            const float* q0 = xs + (s*16 + qr) * 20;
            const float* q1 = q0 + 8 * 20;
            #pragma unroll
            for (int j = 0; j < 2; j++) {
                a[s][j][0] = rna(q0[8*j + qc]);
                a[s][j][1] = rna(q1[8*j + qc]);
                a[s][j][2] = rna(q0[8*j + qc + 4]);
                a[s][j][3] = rna(q1[8*j + qc + 4]);
            }
            a[s][2][0] = rna(q0[16 + qc]);
            a[s][2][1] = rna(q1[16 + qc]);
            a[s][2][2] = 0u;
            a[s][2][3] = 0u;
        }

        // ---- phase 2: stage 1 for all subtiles: h = relu(X @ M1 + c1) ----
        #pragma unroll
        for (int s = 0; s < 4; s++) {
            float* hws = hw + s * (16 * HST);
            #pragma unroll
            for (int i = 0; i < 3; i++) {
                float c[4] = { bi1[i][0], bi1[i][1], bi1[i][0], bi1[i][1] };
                mma8(c, a[s][0], b1f[0][i]);
                mma8(c, a[s][1], b1f[1][i]);
                mma8(c, a[s][2], b1f[2][i]);
                int col = 8*i + 2*qc;     // cols 20,22 land in HST=24 scratch
                float2 v0 = make_float2(fmaxf(c[0], 0.f), fmaxf(c[1], 0.f));
                float2 v1 = make_float2(fmaxf(c[2], 0.f), fmaxf(c[3], 0.f));
                *(float2*)&hws[qr*HST + col]       = v0;
                *(float2*)&hws[(qr + 8)*HST + col] = v1;
            }
        }
        __syncwarp();

        // ---- phase 3: layout conversion for all subtiles ----
        uint32_t a2[4][3][4];
        #pragma unroll
        for (int s = 0; s < 4; s++) {
            const float* hws = hw + s * (16 * HST);
            #pragma unroll
            for (int j = 0; j < 3; j++) {
                a2[s][j][0] = rna(hws[qr*HST + 8*j + qc]);
                a2[s][j][1] = rna(hws[(qr + 8)*HST + 8*j + qc]);
                a2[s][j][2] = rna(hws[qr*HST + 8*j + qc + 4]);
                a2[s][j][3] = rna(hws[(qr + 8)*HST + 8*j + qc + 4]);
            }
        }
        __syncwarp();    // h reads done before next iteration overwrites

        // ---- phase 4: stage 2 for all subtiles: h3 = h @ W^T + b ----
        #pragma unroll
        for (int s = 0; s < 4; s++) {
            bool v0ok = (Rt + s*16 + qr)     < nrows;
            bool v1ok = (Rt + s*16 + qr + 8) < nrows;
            #pragma unroll
            for (int i = 0; i < 3; i++) {
                float c[4] = { bi2[i][0], bi2[i][1], bi2[i][0], bi2[i][1] };
                mma8(c, a2[s][0], b2f[0][i]);
                mma8(c, a2[s][1], b2f[1][i]);
                mma8(c, a2[s][2], b2f[2][i]);
                if (v0ok) { aS0 += c[0] + c[1]; aA0 += fabsf(c[0]) + fabsf(c[1]); }
                if (v1ok) { aS1 += c[2] + c[3]; aA1 += fabsf(c[2]) + fabsf(c[3]); }
            }
        }
        p ^= 1;
    }
    asm volatile("cp.async.wait_group 0;" ::: "memory");   // drain tail prefetch

    // ---- CTA reduce ----
    float accS = aS0 + aS1, accA = aA0 + aA1;
    #pragma unroll
    for (int o = 16; o > 0; o >>= 1) {
        accS += __shfl_down_sync(0xFFFFFFFFu, accS, o);
        accA += __shfl_down_sync(0xFFFFFFFFu, accA, o);
    }
    if (lane == 0) { s_rs[wid] = (double)accS; s_ra[wid] = (double)accA; }
    __syncthreads();

    if (t == 0) {
        double S = s_rs[0] + s_rs[1] + s_rs[2] + s_rs[3];
        double A = s_ra[0] + s_ra[1] + s_ra[2] + s_ra[3];
        g_psum[blockIdx.x] = S;
        g_pabs[blockIdx.x] = A;
        __threadfence();
        unsigned v = atomicAdd(&g_done, 1u);
        s_last = (v == gridDim.x - 1) ? 1 : 0;
    }
    __syncthreads();

    // ---- last CTA: global reduce + exact halving count + write scalar ----
    if (s_last) {
        __threadfence();
        double S = 0.0, A = 0.0;
        for (int i = t; i < (int)gridDim.x; i += TPB) { S += g_psum[i]; A += g_pabs[i]; }
        double* fsum  = (double*)sX;          // mainloop done: overlay X buffers
        double* fabs_ = fsum + TPB;
        fsum[t] = S; fabs_[t] = A;
        __syncthreads();
        for (int o = TPB/2; o > 0; o >>= 1) {
            if (t < o) { fsum[t] += fsum[t + o]; fabs_[t] += fabs_[t + o]; }
            __syncthreads();
        }
        if (t == 0) {
            float s = (float)fabs_[0];
            int k = 0;
            while (s > 1.0f && k < 300) { s *= 0.5f; k++; }
            out[0] = (float)ldexp(fsum[0], -k);   // sum(h) * 2^-k (exact scale)
            __threadfence();
            g_done = 0;                            // reset for next graph replay
        }
    }
}

// ---------------- launch ----------------
extern "C" void kernel_launch(void* const* d_in, const int* in_sizes, int n_in,
                              void* d_out, int out_size) {
    const float* X  = (const float*)d_in[0];
    const float* W  = (const float*)d_in[1];
    const float* b  = (const float*)d_in[2];
    const float* Wi = (const float*)d_in[3];

    long long nrows = (long long)in_sizes[0] / DD;

    cudaFuncSetAttribute(fused_kernel, cudaFuncAttributeMaxDynamicSharedMemorySize, SMEM_DYN);
    fused_kernel<<<NCTA, TPB, SMEM_DYN>>>(X, W, b, Wi, nrows, (float*)d_out);
}

// round 11
// speedup vs baseline: 1.2206x; 1.2206x over previous
#include <cuda_runtime.h>
#include <stdint.h>
#include <math.h>

#define DD   20
#define TPB  128
#define WPB  4               // warps per block
#define NCTA 608             // 152 SMs x 4 CTAs
#define HST  24              // h smem row stride (floats)

__device__ double   g_psum[NCTA];
__device__ double   g_pabs[NCTA];
__device__ unsigned g_done = 0;

static __device__ __forceinline__ uint32_t f2tf(float f) {   // exact rna (prologue only)
    uint32_t u; asm("cvt.rna.tf32.f32 %0, %1;" : "=r"(u) : "f"(f)); return u;
}
// rna-to-tf32 via mantissa carry (validated bit-exact vs cvt.rna, R9)
static __device__ __forceinline__ uint32_t rna(float f) {
    return __float_as_uint(f) + 0x1000u;
}
static __device__ __forceinline__ void mma8(float* c, const uint32_t* a, const uint32_t* b) {
    asm volatile("mma.sync.aligned.m16n8k8.row.col.f32.tf32.tf32.f32 "
        "{%0,%1,%2,%3}, {%4,%5,%6,%7}, {%8,%9}, {%0,%1,%2,%3};"
        : "+f"(c[0]), "+f"(c[1]), "+f"(c[2]), "+f"(c[3])
        : "r"(a[0]), "r"(a[1]), "r"(a[2]), "r"(a[3]), "r"(b[0]), "r"(b[1]));
}
static __device__ __forceinline__ uint32_t s2u(const void* p) {
    uint32_t a;
    asm("{ .reg .u64 t; cvta.to.shared.u64 t, %1; cvt.u32.u64 %0, t; }" : "=r"(a) : "l"(p));
    return a;
}
// per-warp 32-row tile prefetch: 2560B = 5 coalesced 16B cp.async per lane
// 32-bit offsets: X spans nrows*80 < 2^31 bytes.
static __device__ __forceinline__ void issue_tile(const char* Xb, uint32_t tile,
                                                  uint32_t ntiles, uint32_t maxoff,
                                                  uint32_t dst, int lane) {
    if (tile >= ntiles) tile = ntiles - 1;
    uint32_t base = tile * 2560u + (uint32_t)lane * 16u;
    #pragma unroll
    for (int c = 0; c < 5; c++) {
        uint32_t off = base + c * 512u;
        if (off > maxoff) off = maxoff;
        asm volatile("cp.async.cg.shared.global [%0], [%1], 16;"
                     :: "r"(dst + c * 512 + lane * 16), "l"(Xb + off) : "memory");
    }
    asm volatile("cp.async.commit_group;" ::: "memory");
}

__global__ void __launch_bounds__(TPB, 4)
fused_kernel(const float* __restrict__ X, const float* __restrict__ W,
             const float* __restrict__ bvec, const float* __restrict__ Wi,
             long long nrows_ll, float* __restrict__ out) {
    __shared__ float  sW[400], sWi[400], sM1[400], sc1[DD], sb2[DD];
    __shared__ float  sh[WPB][2][16 * HST];              // per-warp h roundtrip
    __shared__ __align__(16) float sX[WPB][2][32 * DD];  // per-warp X double buffer
    __shared__ double s_rs[WPB], s_ra[WPB];
    __shared__ double fs[TPB], fa[TPB];
    __shared__ int    s_last;

    const int t = threadIdx.x;
    const int wid = t >> 5, lane = t & 31;
    const int qr = lane >> 2, qc = lane & 3;
    const uint32_t nrows = (uint32_t)nrows_ll;

    // ---- prologue: M1 = W^T@Wi, c1 = b@Wi + 1 ----
    for (int i = t; i < 400; i += TPB) { sW[i] = W[i]; sWi[i] = Wi[i]; }
    if (t < DD) sb2[t] = bvec[t];
    __syncthreads();
    for (int e = t; e < 400; e += TPB) {
        int k = e / 20, n = e % 20;
        float a = 0.f;
        #pragma unroll
        for (int j = 0; j < 20; j++) a = fmaf(sW[j*20 + k], sWi[j*20 + n], a);
        sM1[e] = a;
    }
    if (t < DD) {
        float a = 1.f;
        #pragma unroll
        for (int j = 0; j < 20; j++) a = fmaf(sb2[j], sWi[j*20 + t], a);
        sc1[t] = a;
    }
    __syncthreads();

    // ---- constant B fragments (exact rna) + bias C-inits, in regs ----
    uint32_t b1f[3][3][2], b2f[3][3][2];
    float    bi1[3][2], bi2[3][2];
    #pragma unroll
    for (int j = 0; j < 3; j++) {
        int k0 = 8*j + qc, k1 = k0 + 4;
        #pragma unroll
        for (int i = 0; i < 3; i++) {
            int n = 8*i + qr;
            float v0 = (k0 < 20 && n < 20) ? sM1[k0*20 + n] : 0.f;
            float v1 = (k1 < 20 && n < 20) ? sM1[k1*20 + n] : 0.f;
            b1f[j][i][0] = f2tf(v0); b1f[j][i][1] = f2tf(v1);
            float w0 = (k0 < 20 && n < 20) ? sW[n*20 + k0] : 0.f;
            float w1 = (k1 < 20 && n < 20) ? sW[n*20 + k1] : 0.f;
            b2f[j][i][0] = f2tf(w0); b2f[j][i][1] = f2tf(w1);
        }
    }
    #pragma unroll
    for (int i = 0; i < 3; i++) {
        int n0 = 8*i + 2*qc;
        bi1[i][0] = (n0     < 20) ? sc1[n0]     : 0.f;
        bi1[i][1] = (n0 + 1 < 20) ? sc1[n0 + 1] : 0.f;
        bi2[i][0] = (n0     < 20) ? sb2[n0]     : 0.f;
        bi2[i][1] = (n0 + 1 < 20) ? sb2[n0 + 1] : 0.f;
    }

    // ---- mainloop: 32 rows/warp/iter, double buffer + cross-iter pipeline ----
    const uint32_t ntiles = (nrows + 31) >> 5;
    const uint32_t gw = (uint32_t)blockIdx.x * WPB + wid;
    const uint32_t nw = (uint32_t)gridDim.x * WPB;
    const uint32_t maxoff = nrows * 80u - 16u;
    const char* Xb = (const char*)X;
    const uint32_t xs0 = s2u(&sX[wid][0][0]);
    const uint32_t xs1 = s2u(&sX[wid][1][0]);

    float aS0 = 0.f, aS1 = 0.f, aA0 = 0.f, aA1 = 0.f;
    uint32_t a2p[2][3][4];    // previous tile's stage-2 A fragments (pipelined)
    uint32_t Rtp = 0;
    int p = 0;

    // macro-ish lambdas to keep the three phases identical across peel/loop
    auto load_a = [&](const float* xs, uint32_t (*a)[3][4]) {
        #pragma unroll
        for (int s = 0; s < 2; s++) {
            const float* q0 = xs + (s*16 + qr) * 20;
            const float* q1 = q0 + 8 * 20;
            #pragma unroll
            for (int j = 0; j < 2; j++) {
                a[s][j][0] = rna(q0[8*j + qc]);
                a[s][j][1] = rna(q1[8*j + qc]);
                a[s][j][2] = rna(q0[8*j + qc + 4]);
                a[s][j][3] = rna(q1[8*j + qc + 4]);
            }
            a[s][2][0] = rna(q0[16 + qc]);
            a[s][2][1] = rna(q1[16 + qc]);
            a[s][2][2] = 0u;
            a[s][2][3] = 0u;
        }
    };
    auto stage1_conv = [&](uint32_t (*a)[3][4]) {
        #pragma unroll
        for (int s = 0; s < 2; s++) {
            float* hw = sh[wid][s];
            #pragma unroll
            for (int i = 0; i < 3; i++) {
                float c[4] = { bi1[i][0], bi1[i][1], bi1[i][0], bi1[i][1] };
                mma8(c, a[s][0], b1f[0][i]);
                mma8(c, a[s][1], b1f[1][i]);
                mma8(c, a[s][2], b1f[2][i]);
                int col = 8*i + 2*qc;            // cols 20,22 land in HST=24 scratch
                float2 v0 = make_float2(fmaxf(c[0], 0.f), fmaxf(c[1], 0.f));
                float2 v1 = make_float2(fmaxf(c[2], 0.f), fmaxf(c[3], 0.f));
                *(float2*)&hw[qr*HST + col]       = v0;
                *(float2*)&hw[(qr + 8)*HST + col] = v1;
            }
        }
        __syncwarp();
        #pragma unroll
        for (int s = 0; s < 2; s++) {
            const float* hw = sh[wid][s];
            #pragma unroll
            for (int j = 0; j < 3; j++) {
                a2p[s][j][0] = rna(hw[qr*HST + 8*j + qc]);
                a2p[s][j][1] = rna(hw[(qr + 8)*HST + 8*j + qc]);
                a2p[s][j][2] = rna(hw[qr*HST + 8*j + qc + 4]);
                a2p[s][j][3] = rna(hw[(qr + 8)*HST + 8*j + qc + 4]);
            }
        }
        __syncwarp();
    };
    auto stage2_prev = [&]() {
        #pragma unroll
        for (int s = 0; s < 2; s++) {
            bool v0ok = (Rtp + s*16 + qr)     < nrows;
            bool v1ok = (Rtp + s*16 + qr + 8) < nrows;
            #pragma unroll
            for (int i = 0; i < 3; i++) {
                float c[4] = { bi2[i][0], bi2[i][1], bi2[i][0], bi2[i][1] };
                mma8(c, a2p[s][0], b2f[0][i]);
                mma8(c, a2p[s][1], b2f[1][i]);
                mma8(c, a2p[s][2], b2f[2][i]);
                if (v0ok) { aS0 += c[0] + c[1]; aA0 += fabsf(c[0]) + fabsf(c[1]); }
                if (v1ok) { aS1 += c[2] + c[3]; aA1 += fabsf(c[2]) + fabsf(c[3]); }
            }
        }
    };

    if (gw < ntiles) {
        issue_tile(Xb, gw,      ntiles, maxoff, xs0, lane);
        issue_tile(Xb, gw + nw, ntiles, maxoff, xs1, lane);

        // ---- peeled first iteration: front half only ----
        asm volatile("cp.async.wait_group 1;" ::: "memory");
        __syncwarp();
        {
            uint32_t a[2][3][4];
            load_a(&sX[wid][0][0], a);
            stage1_conv(a);
            Rtp = gw << 5;
        }
        p = 1;

        // ---- steady state: stage2(t-1) interleaved between loadA(t) and stage1(t) ----
        for (uint32_t tl = gw + nw; tl < ntiles; tl += nw) {
            issue_tile(Xb, tl + nw, ntiles, maxoff, p ? xs0 : xs1, lane);
            asm volatile("cp.async.wait_group 1;" ::: "memory");
            __syncwarp();

            uint32_t a[2][3][4];
            load_a(p ? &sX[wid][1][0] : &sX[wid][0][0], a);
            stage2_prev();                     // independent MMA work covers loadA latency
            stage1_conv(a);                    // writes new a2p
            Rtp = tl << 5;
            p ^= 1;
        }

        stage2_prev();                         // drain the pipelined tail
    }
    asm volatile("cp.async.wait_group 0;" ::: "memory");   // drain tail prefetch

    // ---- CTA reduce ----
    float accS = aS0 + aS1, accA = aA0 + aA1;
    #pragma unroll
    for (int o = 16; o > 0; o >>= 1) {
        accS += __shfl_down_sync(0xFFFFFFFFu, accS, o);
        accA += __shfl_down_sync(0xFFFFFFFFu, accA, o);
    }
    if (lane == 0) { s_rs[wid] = (double)accS; s_ra[wid] = (double)accA; }
    __syncthreads();

    if (t == 0) {
        double S = s_rs[0] + s_rs[1] + s_rs[2] + s_rs[3];
        double A = s_ra[0] + s_ra[1] + s_ra[2] + s_ra[3];
        g_psum[blockIdx.x] = S;
        g_pabs[blockIdx.x] = A;
        __threadfence();
        unsigned v = atomicAdd(&g_done, 1u);
        s_last = (v == gridDim.x - 1) ? 1 : 0;
    }
    __syncthreads();

    // ---- last CTA: global reduce + exact halving count + write scalar ----
    if (s_last) {
        __threadfence();
        double S = 0.0, A = 0.0;
        for (int i = t; i < (int)gridDim.x; i += TPB) { S += g_psum[i]; A += g_pabs[i]; }
        fs[t] = S; fa[t] = A;
        __syncthreads();
        for (int o = TPB/2; o > 0; o >>= 1) {
            if (t < o) { fs[t] += fs[t + o]; fa[t] += fa[t + o]; }
            __syncthreads();
        }
        if (t == 0) {
            float s = (float)fa[0];
            int k = 0;
            while (s > 1.0f && k < 300) { s *= 0.5f; k++; }
            out[0] = (float)ldexp(fs[0], -k);   // sum(h) * 2^-k (exact scale)
            __threadfence();
            g_done = 0;                          // reset for next graph replay
        }
    }
}

// ---------------- launch ----------------
extern "C" void kernel_launch(void* const* d_in, const int* in_sizes, int n_in,
                              void* d_out, int out_size) {
    const float* X  = (const float*)d_in[0];
    const float* W  = (const float*)d_in[1];
    const float* b  = (const float*)d_in[2];
    const float* Wi = (const float*)d_in[3];

    long long nrows = (long long)in_sizes[0] / DD;

    fused_kernel<<<NCTA, TPB>>>(X, W, b, Wi, nrows, (float*)d_out);
}